// round 16
// baseline (speedup 1.0000x reference)
#include <cuda_runtime.h>
#include <cuda_fp16.h>
#include <cstdint>

#define HW 3136
#define EPS 1e-5f
#define NPATCH 3136   // 16 b * 4 g * 7 * 7

// mid1 padded layout: [ch][58 rows][60 cols]; data at [row+1][col+2].
// Borders are NEVER written -> stay zero from static zero-init (module load),
// so k2's 3x3 halo loads need no bounds checks. Interior is fully rewritten
// every launch (k1 for active patches, zero_inactive for inactive) -> replay-safe.
#define M1W 60
#define M1CH (58 * 60)

// Scratch (device globals: no runtime allocation allowed). fp16 intermediates.
__device__ __half g_mid1[16 * 128 * M1CH];   // zero-initialized; borders stay 0
__device__ __half g_mid2[16 * 128 * HW];
__device__ int g_acnt[4];          // active count per group
__device__ int g_lista[4 * 784];   // per-group active patch ids

// ---- packed f32x2 helpers (sm_103a) ----
__device__ __forceinline__ unsigned long long pk2(float a, float b) {
    unsigned long long r;
    asm("mov.b64 %0, {%1, %2};" : "=l"(r) : "f"(a), "f"(b));
    return r;
}
__device__ __forceinline__ void fma2(unsigned long long& d, unsigned long long a,
                                     unsigned long long b) {
    asm("fma.rn.f32x2 %0, %1, %2, %0;" : "+l"(d) : "l"(a), "l"(b));
}
__device__ __forceinline__ float2 upk2(unsigned long long v) {
    float2 r;
    asm("mov.b64 {%0, %1}, %2;" : "=f"(r.x), "=f"(r.y) : "l"(v));
    return r;
}

// ---------------------------------------------------------------------------
// prep: bucket active patches by group (feeds k1/k2 only)
// ---------------------------------------------------------------------------
__global__ void prep(const float* __restrict__ mask) {
    __shared__ int cnt[4];
    int t = threadIdx.x;
    if (t < 4) cnt[t] = 0;
    __syncthreads();
    for (int i = t; i < NPATCH; i += blockDim.x) {
        int g = (i / 49) & 3;
        if (mask[i] != 0.f) {
            int p = atomicAdd(&cnt[g], 1);
            g_lista[g * 784 + p] = i;
        }
    }
    __syncthreads();
    if (t < 4) g_acnt[t] = cnt[t];
}

// ---------------------------------------------------------------------------
// zero_inactive: zero mid1 interior for inactive patches (k2 halo reads them).
// ---------------------------------------------------------------------------
__global__ __launch_bounds__(224) void zero_inactive(const float* __restrict__ mask) {
    const int t = threadIdx.x, blk = blockIdx.x;
    const int w = t >> 5, l = t & 31;
    const int packed = blk * 7 + w;
    if (mask[packed] != 0.f) return;
    const int pc = packed % 7;
    const int pr = (packed / 7) % 7;
    const int g = (packed / 49) & 3;
    const int b = packed / 196;
    const int r = l >> 2, cp = l & 3;
    __half* op = g_mid1 + (size_t)(b * 128 + g * 32) * M1CH
               + (pr * 8 + r + 1) * M1W + pc * 8 + cp * 2 + 2;
    __half2 z = __floats2half2_rn(0.f, 0.f);
#pragma unroll
    for (int j = 0; j < 32; j++) *(__half2*)(op + (size_t)j * M1CH) = z;
}

// Common decode: 224 threads = 7 warps; warp takes an ACTIVE patch from its
// group's list. lane: r=l>>2 row, cp=l&3 col-pair; thread owns 2 pixels.

// ---------------------------------------------------------------------------
// K1: 1x1 conv (128 -> 8 oc per block) + BN1 + ReLU + mask premult -> fp16
// Software-pipelined ping-pong over 8-ic chunks; writes padded mid1.
// grid = 4 qc * 4 g * 112 pb; active patches only
// ---------------------------------------------------------------------------
__global__ __launch_bounds__(224, 4) void k1(const float* __restrict__ x,
                                             const float* __restrict__ mask,
                                             const float* __restrict__ w1,
                                             const float* __restrict__ bg1,
                                             const float* __restrict__ bb1,
                                             const float* __restrict__ bm1,
                                             const float* __restrict__ bv1) {
    __shared__ __align__(16) float ws[1024];  // [ic][8]

    const int t = threadIdx.x, blk = blockIdx.x;
    const int qc = blk & 3;
    const int gb = blk >> 2;
    const int g = gb / 112, pb = gb % 112;
    const int nact = g_acnt[g];
    if (pb * 7 >= nact) return;

    for (int e = t; e < 1024; e += 224) {
        int j = e >> 7, ic = e & 127;
        ws[ic * 8 + j] = w1[(g * 32 + qc * 8 + j) * 128 + ic];
    }
    __syncthreads();

    const int w = t >> 5, l = t & 31;
    const int idx = pb * 7 + w;
    if (idx >= nact) return;
    const int packed = g_lista[g * 784 + idx];
    const int pc = packed % 7;
    const int pr = (packed / 7) % 7;
    const int b = packed / 196;
    const float m = mask[packed];

    const int r = l >> 2, cp = l & 3;
    const int grow = pr * 8 + r;
    const int col = pc * 8 + cp * 2;

    const float* xp = x + (size_t)(b * 512 + g * 128) * HW + grow * 56 + col;
    __half* op = g_mid1 + (size_t)(b * 128 + g * 32 + qc * 8) * M1CH
               + (grow + 1) * M1W + col + 2;

    unsigned long long A0[4], A1[4];
#pragma unroll
    for (int j = 0; j < 4; j++) { A0[j] = 0ull; A1[j] = 0ull; }

    float2 xa[8], xb[8];
#pragma unroll
    for (int u = 0; u < 8; u++) xa[u] = *(const float2*)(xp + (size_t)u * HW);

#pragma unroll
    for (int it = 0; it < 8; it++) {
        const int icA = it * 16;
        const int icB = icA + 8;
#pragma unroll
        for (int u = 0; u < 8; u++)
            xb[u] = *(const float2*)(xp + (size_t)(icB + u) * HW);
#pragma unroll
        for (int u = 0; u < 8; u++) {
            const ulonglong2* wp = (const ulonglong2*)(ws + (icA + u) * 8);
            ulonglong2 q0 = wp[0];
            ulonglong2 q1 = wp[1];
            unsigned long long xx0 = pk2(xa[u].x, xa[u].x);
            unsigned long long xx1 = pk2(xa[u].y, xa[u].y);
            fma2(A0[0], xx0, q0.x); fma2(A0[1], xx0, q0.y);
            fma2(A0[2], xx0, q1.x); fma2(A0[3], xx0, q1.y);
            fma2(A1[0], xx1, q0.x); fma2(A1[1], xx1, q0.y);
            fma2(A1[2], xx1, q1.x); fma2(A1[3], xx1, q1.y);
        }
        if (it < 7) {
#pragma unroll
            for (int u = 0; u < 8; u++)
                xa[u] = *(const float2*)(xp + (size_t)(icA + 16 + u) * HW);
        }
#pragma unroll
        for (int u = 0; u < 8; u++) {
            const ulonglong2* wp = (const ulonglong2*)(ws + (icB + u) * 8);
            ulonglong2 q0 = wp[0];
            ulonglong2 q1 = wp[1];
            unsigned long long xx0 = pk2(xb[u].x, xb[u].x);
            unsigned long long xx1 = pk2(xb[u].y, xb[u].y);
            fma2(A0[0], xx0, q0.x); fma2(A0[1], xx0, q0.y);
            fma2(A0[2], xx0, q1.x); fma2(A0[3], xx0, q1.y);
            fma2(A1[0], xx1, q0.x); fma2(A1[1], xx1, q0.y);
            fma2(A1[2], xx1, q1.x); fma2(A1[3], xx1, q1.y);
        }
    }
#pragma unroll
    for (int p = 0; p < 4; p++) {
        float2 u0 = upk2(A0[p]);
        float2 u1 = upk2(A1[p]);
        float a0[2] = {u0.x, u0.y}, a1[2] = {u1.x, u1.y};
#pragma unroll
        for (int jj = 0; jj < 2; jj++) {
            int j = p * 2 + jj;
            int c = g * 32 + qc * 8 + j;
            float s = bg1[c] * rsqrtf(bv1[c] + EPS);
            float bb = bb1[c] - bm1[c] * s;
            float v0 = fmaxf(fmaf(m * a0[jj], s, bb), 0.f) * m;
            float v1 = fmaxf(fmaf(m * a1[jj], s, bb), 0.f) * m;
            *(__half2*)(op + (size_t)j * M1CH) = __floats2half2_rn(v0, v1);
        }
    }
}

// ---------------------------------------------------------------------------
// K2: 3x3 conv (32 -> 8 oc per block, pad 1) + BN2 + ReLU + mask -> fp16
// Reads padded mid1 -> ALL halo loads unconditional (no predicates/selects).
// grid = 4 qc * 4 g * 112 pb
// ---------------------------------------------------------------------------
__global__ __launch_bounds__(224, 4) void k2(const float* __restrict__ mask,
                                             const float* __restrict__ w2,
                                             const float* __restrict__ bg2,
                                             const float* __restrict__ bb2,
                                             const float* __restrict__ bm2,
                                             const float* __restrict__ bv2) {
    __shared__ __align__(16) float ws[2304];  // [ic][9 tap][8 oc]

    const int t = threadIdx.x, blk = blockIdx.x;
    const int qc = blk & 3;
    const int gb = blk >> 2;
    const int g = gb / 112, pb = gb % 112;
    const int nact = g_acnt[g];
    if (pb * 7 >= nact) return;

    for (int e = t; e < 2304; e += 224) {
        int j = e / 288;
        int rem = e - j * 288;
        int ic = rem / 9;
        int k = rem - ic * 9;
        ws[(ic * 9 + k) * 8 + j] = w2[((g * 32 + qc * 8 + j) * 32 + ic) * 9 + k];
    }
    __syncthreads();

    const int w = t >> 5, l = t & 31;
    const int idx = pb * 7 + w;
    if (idx >= nact) return;
    const int packed = g_lista[g * 784 + idx];
    const int pc = packed % 7;
    const int pr = (packed / 7) % 7;
    const int b = packed / 196;
    const float m = mask[packed];

    const int r = l >> 2, cp = l & 3;
    const int grow = pr * 8 + r;
    const int col = pc * 8 + cp * 2;

    __half* op = g_mid2 + (size_t)(b * 128 + g * 32 + qc * 8) * HW + grow * 56 + col;
    // padded mid1: center pixel0 at [grow+1][col+2]
    const __half* mb = g_mid1 + (size_t)(b * 128 + g * 32) * M1CH
                     + (grow + 1) * M1W + col + 2;

    unsigned long long A0[4], A1[4];
#pragma unroll
    for (int j = 0; j < 4; j++) { A0[j] = 0ull; A1[j] = 0ull; }

#pragma unroll 2
    for (int ic = 0; ic < 32; ic++) {
        const __half* pic = mb + (size_t)ic * M1CH;
        float xm[3], x2[3];
        float2 xc[3];
#pragma unroll
        for (int dy = 0; dy < 3; dy++) {
            const __half* p = pic + (dy - 1) * M1W;
            xm[dy] = __half2float(p[-1]);
            xc[dy] = __half22float2(*(const __half2*)p);
            x2[dy] = __half2float(p[2]);
        }
#pragma unroll
        for (int dy = 0; dy < 3; dy++) {
            const ulonglong2* wp = (const ulonglong2*)(ws + (ic * 9 + dy * 3) * 8);
            ulonglong2 ta = wp[0];   // tap dx=0, oc pairs 0,1
            ulonglong2 tA = wp[1];   // tap dx=0, oc pairs 2,3
            ulonglong2 tb = wp[2];   // tap dx=1, oc pairs 0,1
            ulonglong2 tB = wp[3];   // tap dx=1, oc pairs 2,3
            ulonglong2 tc = wp[4];   // tap dx=2, oc pairs 0,1
            ulonglong2 tC = wp[5];   // tap dx=2, oc pairs 2,3
            unsigned long long t00 = pk2(xm[dy], xm[dy]);
            unsigned long long t11 = pk2(xc[dy].x, xc[dy].x);
            unsigned long long t22 = pk2(xc[dy].y, xc[dy].y);
            unsigned long long t33 = pk2(x2[dy], x2[dy]);
            fma2(A0[0], t00, ta.x); fma2(A0[1], t00, ta.y);
            fma2(A0[2], t00, tA.x); fma2(A0[3], t00, tA.y);
            fma2(A0[0], t11, tb.x); fma2(A0[1], t11, tb.y);
            fma2(A0[2], t11, tB.x); fma2(A0[3], t11, tB.y);
            fma2(A0[0], t22, tc.x); fma2(A0[1], t22, tc.y);
            fma2(A0[2], t22, tC.x); fma2(A0[3], t22, tC.y);
            fma2(A1[0], t11, ta.x); fma2(A1[1], t11, ta.y);
            fma2(A1[2], t11, tA.x); fma2(A1[3], t11, tA.y);
            fma2(A1[0], t22, tb.x); fma2(A1[1], t22, tb.y);
            fma2(A1[2], t22, tB.x); fma2(A1[3], t22, tB.y);
            fma2(A1[0], t33, tc.x); fma2(A1[1], t33, tc.y);
            fma2(A1[2], t33, tC.x); fma2(A1[3], t33, tC.y);
        }
    }
#pragma unroll
    for (int p = 0; p < 4; p++) {
        float2 u0 = upk2(A0[p]);
        float2 u1 = upk2(A1[p]);
        float a0[2] = {u0.x, u0.y}, a1[2] = {u1.x, u1.y};
#pragma unroll
        for (int jj = 0; jj < 2; jj++) {
            int j = p * 2 + jj;
            int c = g * 32 + qc * 8 + j;
            float s = bg2[c] * rsqrtf(bv2[c] + EPS);
            float bb = bb2[c] - bm2[c] * s;
            float v0 = fmaxf(fmaf(a0[jj], s, bb), 0.f) * m;
            float v1 = fmaxf(fmaf(a1[jj], s, bb), 0.f) * m;
            *(__half2*)(op + (size_t)j * HW) = __floats2half2_rn(v0, v1);
        }
    }
}

// ---------------------------------------------------------------------------
// K3: 1x1 conv (32 -> 8 oc per block) + BN3 + residual + ReLU (all patches)
// L2-prefetch of the residual at kernel start; pipelined conv loop.
// grid = (b,g,pr,qc in 0..15)
// ---------------------------------------------------------------------------
__global__ __launch_bounds__(224, 4) void k3(const float* __restrict__ x,
                                             const float* __restrict__ mask,
                                             const float* __restrict__ w3,
                                             const float* __restrict__ bg3,
                                             const float* __restrict__ bb3,
                                             const float* __restrict__ bm3,
                                             const float* __restrict__ bv3,
                                             float* __restrict__ out) {
    __shared__ __align__(16) float ws[256];  // [ic][8]

    const int t = threadIdx.x, blk = blockIdx.x;
    const int qc = blk & 15;
    const int rest = blk >> 4;
    const int pr = rest % 7;
    const int bg = rest / 7;
    const int g = bg & 3, b = bg >> 2;

    const int w = t >> 5, l = t & 31;
    const int r = l >> 2, cp = l & 3;
    const int grow = pr * 8 + r;
    const int col = w * 8 + cp * 2;

    const float* resp = x + (size_t)(b * 512 + g * 128 + qc * 8) * HW + grow * 56 + col;
    // warm L2 for the residual epilogue loads (no register cost)
#pragma unroll
    for (int j = 0; j < 8; j++)
        asm volatile("prefetch.global.L2 [%0];" :: "l"(resp + (size_t)j * HW));

    for (int e = t; e < 256; e += 224) {
        int j = e >> 5, ic = e & 31;
        ws[ic * 8 + j] = w3[(g * 128 + qc * 8 + j) * 32 + ic];
    }
    __syncthreads();

    const float m = mask[((b * 4 + g) * 7 + pr) * 7 + w];
    float* op = out + (size_t)(b * 512 + g * 128 + qc * 8) * HW + grow * 56 + col;

    float sc[8], bi[8];
#pragma unroll
    for (int j = 0; j < 8; j++) {
        int c = g * 128 + qc * 8 + j;
        float s = bg3[c] * rsqrtf(bv3[c] + EPS);
        sc[j] = s;
        bi[j] = bb3[c] - bm3[c] * s;
    }

    if (m != 0.f) {
        const __half* mp = g_mid2 + (size_t)(b * 128 + g * 32) * HW + grow * 56 + col;
        unsigned long long A0[4], A1[4];
#pragma unroll
        for (int j = 0; j < 4; j++) { A0[j] = 0ull; A1[j] = 0ull; }

        float2 xa[8], xb[8];
#pragma unroll
        for (int u = 0; u < 8; u++)
            xa[u] = __half22float2(*(const __half2*)(mp + (size_t)u * HW));

#pragma unroll
        for (int it = 0; it < 2; it++) {
            const int icA = it * 16;
            const int icB = icA + 8;
#pragma unroll
            for (int u = 0; u < 8; u++)
                xb[u] = __half22float2(*(const __half2*)(mp + (size_t)(icB + u) * HW));
#pragma unroll
            for (int u = 0; u < 8; u++) {
                const ulonglong2* wp = (const ulonglong2*)(ws + (icA + u) * 8);
                ulonglong2 q0 = wp[0];
                ulonglong2 q1 = wp[1];
                unsigned long long xx0 = pk2(xa[u].x, xa[u].x);
                unsigned long long xx1 = pk2(xa[u].y, xa[u].y);
                fma2(A0[0], xx0, q0.x); fma2(A0[1], xx0, q0.y);
                fma2(A0[2], xx0, q1.x); fma2(A0[3], xx0, q1.y);
                fma2(A1[0], xx1, q0.x); fma2(A1[1], xx1, q0.y);
                fma2(A1[2], xx1, q1.x); fma2(A1[3], xx1, q1.y);
            }
            if (it < 1) {
#pragma unroll
                for (int u = 0; u < 8; u++)
                    xa[u] = __half22float2(*(const __half2*)(mp + (size_t)(icA + 16 + u) * HW));
            }
#pragma unroll
            for (int u = 0; u < 8; u++) {
                const ulonglong2* wp = (const ulonglong2*)(ws + (icB + u) * 8);
                ulonglong2 q0 = wp[0];
                ulonglong2 q1 = wp[1];
                unsigned long long xx0 = pk2(xb[u].x, xb[u].x);
                unsigned long long xx1 = pk2(xb[u].y, xb[u].y);
                fma2(A0[0], xx0, q0.x); fma2(A0[1], xx0, q0.y);
                fma2(A0[2], xx0, q1.x); fma2(A0[3], xx0, q1.y);
                fma2(A1[0], xx1, q0.x); fma2(A1[1], xx1, q0.y);
                fma2(A1[2], xx1, q1.x); fma2(A1[3], xx1, q1.y);
            }
        }
#pragma unroll
        for (int p = 0; p < 4; p++) {
            float2 u0 = upk2(A0[p]);
            float2 u1 = upk2(A1[p]);
            float a0[2] = {u0.x, u0.y}, a1[2] = {u1.x, u1.y};
#pragma unroll
            for (int jj = 0; jj < 2; jj++) {
                int j = p * 2 + jj;
                float2 res = *(const float2*)(resp + (size_t)j * HW);
                float v0 = fmaxf(fmaf(a0[jj], sc[j], bi[j]) + res.x, 0.f);
                float v1 = fmaxf(fmaf(a1[jj], sc[j], bi[j]) + res.y, 0.f);
                *(float2*)(op + (size_t)j * HW) = make_float2(v0, v1);
            }
        }
    } else {
#pragma unroll
        for (int j = 0; j < 8; j++) {
            float2 res = *(const float2*)(resp + (size_t)j * HW);
            float v0 = fmaxf(bi[j] + res.x, 0.f);
            float v1 = fmaxf(bi[j] + res.y, 0.f);
            *(float2*)(op + (size_t)j * HW) = make_float2(v0, v1);
        }
    }
}

// ---------------------------------------------------------------------------
extern "C" void kernel_launch(void* const* d_in, const int* in_sizes, int n_in,
                              void* d_out, int out_size) {
    const float* x    = (const float*)d_in[0];
    const float* mask = (const float*)d_in[1];
    const float* w1   = (const float*)d_in[2];
    const float* g1 = (const float*)d_in[3];
    const float* b1 = (const float*)d_in[4];
    const float* m1 = (const float*)d_in[5];
    const float* v1 = (const float*)d_in[6];
    const float* w2   = (const float*)d_in[7];
    const float* g2 = (const float*)d_in[8];
    const float* b2 = (const float*)d_in[9];
    const float* m2 = (const float*)d_in[10];
    const float* v2 = (const float*)d_in[11];
    const float* w3   = (const float*)d_in[12];
    const float* g3 = (const float*)d_in[13];
    const float* b3 = (const float*)d_in[14];
    const float* m3 = (const float*)d_in[15];
    const float* v3 = (const float*)d_in[16];
    float* out = (float*)d_out;

    prep<<<1, 1024>>>(mask);
    zero_inactive<<<448, 224>>>(mask);

    k1<<<4 * 4 * 112, 224>>>(x, mask, w1, g1, b1, m1, v1);
    k2<<<4 * 4 * 112, 224>>>(mask, w2, g2, b2, m2, v2);
    k3<<<16 * 4 * 7 * 16, 224>>>(x, mask, w3, g3, b3, m3, v3, out);
}